// round 2
// baseline (speedup 1.0000x reference)
#include <cuda_runtime.h>
#include <cstdint>

typedef unsigned long long ull;

#define L 512
#define H 1024
#define C 2

// Scratch (no allocation allowed in kernel_launch)
__device__ float g_ap[L * H];      // a_proj + b1, [l][o]
__device__ float g_bp[L * H];      // b_proj,      [l][o]
__device__ float g_f[L * L * C];   // unsymmetrized logits f[i][j][c]

// ---- packed f32x2 helpers (Blackwell FFMA2 path) ----
__device__ __forceinline__ ull ffma2(ull a, ull b, ull c) {
    ull d;
    asm("fma.rn.f32x2 %0, %1, %2, %3;" : "=l"(d) : "l"(a), "l"(b), "l"(c));
    return d;
}
__device__ __forceinline__ ull fadd2(ull a, ull b) {
    ull d;
    asm("add.rn.f32x2 %0, %1, %2;" : "=l"(d) : "l"(a), "l"(b));
    return d;
}
__device__ __forceinline__ float2 u2f2(ull u) {
    float2 v;
    asm("mov.b64 {%0, %1}, %2;" : "=f"(v.x), "=f"(v.y) : "l"(u));
    return v;
}
// two MUFU.TANH on a packed pair
__device__ __forceinline__ ull tanh2(ull x) {
    ull r;
    asm("{\n\t"
        ".reg .f32 lo, hi;\n\t"
        "mov.b64 {lo, hi}, %1;\n\t"
        "tanh.approx.f32 lo, lo;\n\t"
        "tanh.approx.f32 hi, hi;\n\t"
        "mov.b64 %0, {lo, hi};\n\t"
        "}" : "=l"(r) : "l"(x));
    return r;
}

// ============================================================
// Kernel 1: ap/bp = x @ W1 (both halves), +b1 folded into ap.
// Tile: 64 l x 32 o per block, 256 threads, each thread 4l x 2o,
// accumulators packed over k-parity (f32x2).
// ============================================================
#define K1_BM 64
#define K1_BN 32
#define K1_KC 32
#define K1_PAD 34   // 136B rows: 8B aligned, conflict-light

__global__ __launch_bounds__(256) void k1_gemm(const float* __restrict__ x,
                                               const float* __restrict__ W1,
                                               const float* __restrict__ b1) {
    __shared__ __align__(16) float xs[K1_BM][K1_PAD];
    __shared__ __align__(16) float was[K1_BN][K1_PAD];
    __shared__ __align__(16) float wbs[K1_BN][K1_PAD];

    const int t = threadIdx.x;
    const int tx = t & 15;      // o-dim
    const int ty = t >> 4;      // l-dim
    const int lblk = blockIdx.y * K1_BM;
    const int oblk = blockIdx.x * K1_BN;

    ull accA[4][2], accB[4][2];
#pragma unroll
    for (int u = 0; u < 4; u++)
#pragma unroll
        for (int v = 0; v < 2; v++) { accA[u][v] = 0ull; accB[u][v] = 0ull; }

    for (int kb = 0; kb < H; kb += K1_KC) {
        // x tile: 64 rows x 32 k = 1024 float2
#pragma unroll
        for (int q = t; q < K1_BM * K1_KC / 2; q += 256) {
            int r = q >> 4, c = q & 15;
            *(float2*)&xs[r][c * 2] =
                *(const float2*)&x[(lblk + r) * H + kb + c * 2];
        }
        // W1 tiles: 32 rows x 32 k each (wa and wb halves)
#pragma unroll
        for (int q = t; q < K1_BN * K1_KC / 2; q += 256) {
            int r = q >> 4, c = q & 15;
            const float* wrow = &W1[(oblk + r) * (2 * H) + kb];
            *(float2*)&was[r][c * 2] = *(const float2*)&wrow[c * 2];
            *(float2*)&wbs[r][c * 2] = *(const float2*)&wrow[H + c * 2];
        }
        __syncthreads();

#pragma unroll
        for (int kp = 0; kp < K1_KC / 2; kp++) {
            ull xv[4], wav[2], wbv[2];
#pragma unroll
            for (int u = 0; u < 4; u++)
                xv[u] = *(const ull*)&xs[ty * 4 + u][kp * 2];
#pragma unroll
            for (int v = 0; v < 2; v++) {
                wav[v] = *(const ull*)&was[tx * 2 + v][kp * 2];
                wbv[v] = *(const ull*)&wbs[tx * 2 + v][kp * 2];
            }
#pragma unroll
            for (int u = 0; u < 4; u++)
#pragma unroll
                for (int v = 0; v < 2; v++) {
                    accA[u][v] = ffma2(xv[u], wav[v], accA[u][v]);
                    accB[u][v] = ffma2(xv[u], wbv[v], accB[u][v]);
                }
        }
        __syncthreads();
    }

#pragma unroll
    for (int v = 0; v < 2; v++) {
        const int o = oblk + tx * 2 + v;
        const float bv = b1[o];
#pragma unroll
        for (int u = 0; u < 4; u++) {
            const int l = lblk + ty * 4 + u;
            float2 sa = u2f2(accA[u][v]);
            float2 sb = u2f2(accB[u][v]);
            g_ap[l * H + o] = sa.x + sa.y + bv;
            g_bp[l * H + o] = sb.x + sb.y;
        }
    }
}

// ============================================================
// Kernel 2: f[i,j,c] = sum_h tanh(ap[j,h] + bp[i,h]) * W2[c,h]
// Tile: 32i x 32j per block, 256 threads, each thread 2i x 2j pairs,
// h processed in packed pairs; MUFU.TANH is the binding pipe.
// ============================================================
#define K2_T 32
#define K2_HC 32
#define K2_PAD 34

__global__ __launch_bounds__(256) void k2_pair(const float* __restrict__ W2) {
    __shared__ __align__(16) float as[K2_T][K2_PAD];   // ap rows (j)
    __shared__ __align__(16) float bs[K2_T][K2_PAD];   // bp rows (i)
    __shared__ __align__(16) float w2s[2][K2_HC];

    const int t = threadIdx.x;
    const int tx = t & 15;   // j
    const int ty = t >> 4;   // i
    const int jblk = blockIdx.x * K2_T;
    const int iblk = blockIdx.y * K2_T;

    ull acc[2][2][2];   // [iu][jv][c], packed over h-parity
#pragma unroll
    for (int a = 0; a < 2; a++)
#pragma unroll
        for (int b = 0; b < 2; b++)
#pragma unroll
            for (int c = 0; c < 2; c++) acc[a][b][c] = 0ull;

    for (int hb = 0; hb < H; hb += K2_HC) {
#pragma unroll
        for (int q = t; q < K2_T * K2_HC / 2; q += 256) {
            int r = q >> 4, c = q & 15;
            *(float2*)&as[r][c * 2] =
                *(const float2*)&g_ap[(jblk + r) * H + hb + c * 2];
            *(float2*)&bs[r][c * 2] =
                *(const float2*)&g_bp[(iblk + r) * H + hb + c * 2];
        }
        if (t < 32) {
            int rr = t >> 4, cc = t & 15;
            *(float2*)&w2s[rr][cc * 2] =
                *(const float2*)&W2[rr * H + hb + cc * 2];
        }
        __syncthreads();

#pragma unroll
        for (int hp = 0; hp < K2_HC / 2; hp++) {
            ull a0 = *(const ull*)&as[tx][hp * 2];
            ull a1 = *(const ull*)&as[tx + 16][hp * 2];
            ull b0 = *(const ull*)&bs[ty][hp * 2];
            ull b1v = *(const ull*)&bs[ty + 16][hp * 2];
            ull w0 = *(const ull*)&w2s[0][hp * 2];
            ull w1 = *(const ull*)&w2s[1][hp * 2];

            ull t00 = tanh2(fadd2(a0, b0));
            ull t01 = tanh2(fadd2(a1, b0));
            ull t10 = tanh2(fadd2(a0, b1v));
            ull t11 = tanh2(fadd2(a1, b1v));

            acc[0][0][0] = ffma2(t00, w0, acc[0][0][0]);
            acc[0][0][1] = ffma2(t00, w1, acc[0][0][1]);
            acc[0][1][0] = ffma2(t01, w0, acc[0][1][0]);
            acc[0][1][1] = ffma2(t01, w1, acc[0][1][1]);
            acc[1][0][0] = ffma2(t10, w0, acc[1][0][0]);
            acc[1][0][1] = ffma2(t10, w1, acc[1][0][1]);
            acc[1][1][0] = ffma2(t11, w0, acc[1][1][0]);
            acc[1][1][1] = ffma2(t11, w1, acc[1][1][1]);
        }
        __syncthreads();
    }

#pragma unroll
    for (int iu = 0; iu < 2; iu++) {
        const int i = iblk + ty + iu * 16;
#pragma unroll
        for (int jv = 0; jv < 2; jv++) {
            const int j = jblk + tx + jv * 16;
            float2 s0 = u2f2(acc[iu][jv][0]);
            float2 s1 = u2f2(acc[iu][jv][1]);
            float2 o;
            o.x = s0.x + s0.y;
            o.y = s1.x + s1.y;
            *(float2*)&g_f[(i * L + j) * 2] = o;
        }
    }
}

// ============================================================
// Kernel 3: out[i,j,c] = 0.5*(f[i,j,c] + f[j,i,c]) + b2[c]
// ============================================================
__global__ __launch_bounds__(256) void k3_sym(const float* __restrict__ b2,
                                              float* __restrict__ out) {
    const int idx = blockIdx.x * 256 + threadIdx.x;   // over L*L
    const int i = idx >> 9;
    const int j = idx & (L - 1);
    const float2 fij = *(const float2*)&g_f[idx * 2];
    const float2 fji = *(const float2*)&g_f[((j << 9) | i) * 2];
    float2 r;
    r.x = (fij.x + fji.x) * 0.5f + b2[0];
    r.y = (fij.y + fji.y) * 0.5f + b2[1];
    *(float2*)&out[idx * 2] = r;
}

extern "C" void kernel_launch(void* const* d_in, const int* in_sizes, int n_in,
                              void* d_out, int out_size) {
    const float* x  = (const float*)d_in[0];   // lm_output (1,512,1024)
    const float* W1 = (const float*)d_in[1];   // (1024, 2048)
    const float* b1 = (const float*)d_in[2];   // (1024,)
    const float* W2 = (const float*)d_in[3];   // (2, 1024)
    const float* b2 = (const float*)d_in[4];   // (2,)
    float* out = (float*)d_out;                // (1,512,512,2) fp32

    k1_gemm<<<dim3(H / K1_BN, L / K1_BM), 256>>>(x, W1, b1);
    k2_pair<<<dim3(L / K2_T, L / K2_T), 256>>>(W2);
    k3_sym<<<(L * L) / 256, 256>>>(b2, out);
}

// round 3
// speedup vs baseline: 1.3139x; 1.3139x over previous
#include <cuda_runtime.h>
#include <cstdint>

typedef unsigned long long ull;
typedef unsigned int u32;

#define L 512
#define H 1024
#define C 2

// Scratch
__device__ float g_ap[L * H];      // a_proj + b1, [l][o]
__device__ float g_bp[L * H];      // b_proj,      [l][o]
__device__ float g_f[L * L * C];   // unsymmetrized logits f[i][j][c]

// ---- packed f32x2 helpers ----
__device__ __forceinline__ ull ffma2(ull a, ull b, ull c) {
    ull d;
    asm("fma.rn.f32x2 %0, %1, %2, %3;" : "=l"(d) : "l"(a), "l"(b), "l"(c));
    return d;
}
__device__ __forceinline__ ull fadd2(ull a, ull b) {
    ull d;
    asm("add.rn.f32x2 %0, %1, %2;" : "=l"(d) : "l"(a), "l"(b));
    return d;
}
__device__ __forceinline__ float2 u2f2(ull u) {
    float2 v;
    asm("mov.b64 {%0, %1}, %2;" : "=f"(v.x), "=f"(v.y) : "l"(u));
    return v;
}
__device__ __forceinline__ ull tanh2(ull x) {
    ull r;
    asm("{\n\t"
        ".reg .f32 lo, hi;\n\t"
        "mov.b64 {lo, hi}, %1;\n\t"
        "tanh.approx.f32 lo, lo;\n\t"
        "tanh.approx.f32 hi, hi;\n\t"
        "mov.b64 %0, {lo, hi};\n\t"
        "}" : "=l"(r) : "l"(x));
    return r;
}
__device__ __forceinline__ u32 to_tf32(float f) {
    u32 r;
    asm("cvt.rna.tf32.f32 %0, %1;" : "=r"(r) : "f"(f));
    return r;
}
__device__ __forceinline__ void mma_tf32(float c[4], u32 a0, u32 a1, u32 a2, u32 a3,
                                         u32 b0, u32 b1) {
    asm("mma.sync.aligned.m16n8k8.row.col.f32.tf32.tf32.f32 "
        "{%0,%1,%2,%3}, {%4,%5,%6,%7}, {%8,%9}, {%0,%1,%2,%3};"
        : "+f"(c[0]), "+f"(c[1]), "+f"(c[2]), "+f"(c[3])
        : "r"(a0), "r"(a1), "r"(a2), "r"(a3), "r"(b0), "r"(b1));
}

// ============================================================
// Kernel 1: tf32 tensor-core GEMM.
// ap[l,o] = sum_h x[l,h] W1[o,h] (+b1), bp[l,o] = sum_h x[l,h] W1[o,H+h]
// Tile 64l x 32o (both outputs share the x tile), KC=32, 8 warps:
// warp grid 4(m) x 2(n), each warp m16 x n16 => 2 n-atoms x 2 outputs.
// ============================================================
#define G_BM 64
#define G_BN 32
#define G_KC 32
#define G_PAD 36   // 144B rows: float4-aligned, conflict-free frag loads

__global__ __launch_bounds__(256) void k1_mma(const float* __restrict__ x,
                                              const float* __restrict__ W1,
                                              const float* __restrict__ b1) {
    __shared__ __align__(16) float xs[G_BM][G_PAD];
    __shared__ __align__(16) float was[G_BN][G_PAD];
    __shared__ __align__(16) float wbs[G_BN][G_PAD];

    const int t = threadIdx.x;
    const int lane = t & 31;
    const int wid = t >> 5;
    const int gid = lane >> 2;      // group id (row within atom)
    const int tig = lane & 3;       // thread in group (k / col pos)
    const int wm = (wid & 3) * 16;  // warp m offset within tile
    const int wn = (wid >> 2) * 16; // warp n offset within tile
    const int lblk = blockIdx.y * G_BM;
    const int oblk = blockIdx.x * G_BN;

    float accA[2][4], accB[2][4];
#pragma unroll
    for (int na = 0; na < 2; na++)
#pragma unroll
        for (int q = 0; q < 4; q++) { accA[na][q] = 0.f; accB[na][q] = 0.f; }

    for (int kb = 0; kb < H; kb += G_KC) {
        // load + cvt x tile: 64 rows x 32 k = 512 float4, 2 per thread
#pragma unroll
        for (int q = 0; q < 2; q++) {
            int idx = t + q * 256;          // [0,512)
            int r = idx >> 3, c4 = (idx & 7) * 4;
            float4 v = *(const float4*)&x[(lblk + r) * H + kb + c4];
            u32* dst = (u32*)&xs[r][c4];
            dst[0] = to_tf32(v.x); dst[1] = to_tf32(v.y);
            dst[2] = to_tf32(v.z); dst[3] = to_tf32(v.w);
        }
        // W tiles: 32 rows x 32 k each, 256 float4 each, 1 per thread
        {
            int r = t >> 3, c4 = (t & 7) * 4;
            const float* wrow = &W1[(oblk + r) * (2 * H) + kb];
            float4 va = *(const float4*)&wrow[c4];
            float4 vb = *(const float4*)&wrow[H + c4];
            u32* da = (u32*)&was[r][c4];
            da[0] = to_tf32(va.x); da[1] = to_tf32(va.y);
            da[2] = to_tf32(va.z); da[3] = to_tf32(va.w);
            u32* db = (u32*)&wbs[r][c4];
            db[0] = to_tf32(vb.x); db[1] = to_tf32(vb.y);
            db[2] = to_tf32(vb.z); db[3] = to_tf32(vb.w);
        }
        __syncthreads();

#pragma unroll
        for (int ks = 0; ks < G_KC / 8; ks++) {
            const int k0 = ks * 8;
            // A fragment (m16k8): a0=(g,t) a1=(g+8,t) a2=(g,t+4) a3=(g+8,t+4)
            u32 a0 = *(const u32*)&xs[wm + gid][k0 + tig];
            u32 a1 = *(const u32*)&xs[wm + gid + 8][k0 + tig];
            u32 a2 = *(const u32*)&xs[wm + gid][k0 + tig + 4];
            u32 a3 = *(const u32*)&xs[wm + gid + 8][k0 + tig + 4];
#pragma unroll
            for (int na = 0; na < 2; na++) {
                const int nrow = wn + na * 8 + gid;
                u32 bA0 = *(const u32*)&was[nrow][k0 + tig];
                u32 bA1 = *(const u32*)&was[nrow][k0 + tig + 4];
                u32 bB0 = *(const u32*)&wbs[nrow][k0 + tig];
                u32 bB1 = *(const u32*)&wbs[nrow][k0 + tig + 4];
                mma_tf32(accA[na], a0, a1, a2, a3, bA0, bA1);
                mma_tf32(accB[na], a0, a1, a2, a3, bB0, bB1);
            }
        }
        __syncthreads();
    }

    // epilogue: c0=(g,2t) c1=(g,2t+1) c2=(g+8,2t) c3=(g+8,2t+1)
#pragma unroll
    for (int na = 0; na < 2; na++) {
        const int col = oblk + wn + na * 8 + tig * 2;
        const int row0 = lblk + wm + gid;
        const float2 bv = *(const float2*)&b1[col];
        float2 v;
        v.x = accA[na][0] + bv.x; v.y = accA[na][1] + bv.y;
        *(float2*)&g_ap[row0 * H + col] = v;
        v.x = accA[na][2] + bv.x; v.y = accA[na][3] + bv.y;
        *(float2*)&g_ap[(row0 + 8) * H + col] = v;
        v.x = accB[na][0]; v.y = accB[na][1];
        *(float2*)&g_bp[row0 * H + col] = v;
        v.x = accB[na][2]; v.y = accB[na][3];
        *(float2*)&g_bp[(row0 + 8) * H + col] = v;
    }
}

// ============================================================
// Kernel 2: f[i,j,c] = sum_h tanh(ap[j,h] + bp[i,h]) * W2[c,h]
// Tile 16i x 32j, 256 threads (1i x 2j each), HC=64. MUFU-bound.
// ============================================================
#define P_TI 16
#define P_TJ 32
#define P_HC 64
#define P_PAD 66

__global__ __launch_bounds__(256) void k2_pair(const float* __restrict__ W2) {
    __shared__ __align__(16) float as[P_TJ][P_PAD];   // ap rows (j)
    __shared__ __align__(16) float bs[P_TI][P_PAD];   // bp rows (i)
    __shared__ __align__(16) float w2s[2][P_HC];

    const int t = threadIdx.x;
    const int tx = t & 15;   // j
    const int ty = t >> 4;   // i (16 values)
    const int jblk = blockIdx.x * P_TJ;
    const int iblk = blockIdx.y * P_TI;

    ull acc[2][2];   // [jv][c]
    acc[0][0] = acc[0][1] = acc[1][0] = acc[1][1] = 0ull;

    for (int hb = 0; hb < H; hb += P_HC) {
        // as: 32 x 64 floats = 1024 float2, 4/thread
#pragma unroll
        for (int q = 0; q < 4; q++) {
            int idx = t + q * 256;
            int r = idx >> 5, c = (idx & 31) * 2;
            *(float2*)&as[r][c] = *(const float2*)&g_ap[(jblk + r) * H + hb + c];
        }
        // bs: 16 x 64 = 512 float2, 2/thread
#pragma unroll
        for (int q = 0; q < 2; q++) {
            int idx = t + q * 256;
            int r = idx >> 5, c = (idx & 31) * 2;
            *(float2*)&bs[r][c] = *(const float2*)&g_bp[(iblk + r) * H + hb + c];
        }
        // w2: 2 x 64 = 64 float2
        if (t < 64) {
            int r = t >> 5, c = (t & 31) * 2;
            *(float2*)&w2s[r][c] = *(const float2*)&W2[r * H + hb + c];
        }
        __syncthreads();

#pragma unroll 16
        for (int hp = 0; hp < P_HC / 2; hp++) {
            ull a0 = *(const ull*)&as[tx][hp * 2];
            ull a1 = *(const ull*)&as[tx + 16][hp * 2];
            ull b0 = *(const ull*)&bs[ty][hp * 2];
            ull w0 = *(const ull*)&w2s[0][hp * 2];
            ull w1 = *(const ull*)&w2s[1][hp * 2];

            ull t0 = tanh2(fadd2(a0, b0));
            ull t1 = tanh2(fadd2(a1, b0));

            acc[0][0] = ffma2(t0, w0, acc[0][0]);
            acc[0][1] = ffma2(t0, w1, acc[0][1]);
            acc[1][0] = ffma2(t1, w0, acc[1][0]);
            acc[1][1] = ffma2(t1, w1, acc[1][1]);
        }
        __syncthreads();
    }

    const int i = iblk + ty;
#pragma unroll
    for (int jv = 0; jv < 2; jv++) {
        const int j = jblk + tx + jv * 16;
        float2 s0 = u2f2(acc[jv][0]);
        float2 s1 = u2f2(acc[jv][1]);
        float2 o;
        o.x = s0.x + s0.y;
        o.y = s1.x + s1.y;
        *(float2*)&g_f[(i * L + j) * 2] = o;
    }
}

// ============================================================
// Kernel 3: out[i,j,c] = 0.5*(f[i,j,c] + f[j,i,c]) + b2[c]
// ============================================================
__global__ __launch_bounds__(256) void k3_sym(const float* __restrict__ b2,
                                              float* __restrict__ out) {
    const int idx = blockIdx.x * 256 + threadIdx.x;
    const int i = idx >> 9;
    const int j = idx & (L - 1);
    const float2 fij = *(const float2*)&g_f[idx * 2];
    const float2 fji = *(const float2*)&g_f[((j << 9) | i) * 2];
    float2 r;
    r.x = (fij.x + fji.x) * 0.5f + b2[0];
    r.y = (fij.y + fji.y) * 0.5f + b2[1];
    *(float2*)&out[idx * 2] = r;
}

extern "C" void kernel_launch(void* const* d_in, const int* in_sizes, int n_in,
                              void* d_out, int out_size) {
    const float* x  = (const float*)d_in[0];
    const float* W1 = (const float*)d_in[1];
    const float* b1 = (const float*)d_in[2];
    const float* W2 = (const float*)d_in[3];
    const float* b2 = (const float*)d_in[4];
    float* out = (float*)d_out;

    k1_mma<<<dim3(H / G_BN, L / G_BM), 256>>>(x, W1, b1);
    k2_pair<<<dim3(L / P_TJ, L / P_TI), 256>>>(W2);
    k3_sym<<<(L * L) / 256, 256>>>(b2, out);
}